// round 8
// baseline (speedup 1.0000x reference)
#include <cuda_runtime.h>
#include <cuda_bf16.h>
#include <stdint.h>

// units2indices: 80M fp32 bipolar {-1,+1} -> 8M codebook index VALUES stored
// as float32 (harness __output__ dtype is float32). Groups of num_bits=10,
// first element is MSB.
//
// Warp-autonomous ballot transpose, deep-MLP variant:
//  - each warp handles 1280 contiguous floats = 128 groups
//  - 40 coalesced scalar loads front-batched into registers (MLP=40,
//    per-warp outstanding-LDG capacity is ~55)
//  - 40 ballots pack sign bits; lane l keeps masks l and 32+l
//  - phase 2: each lane emits 4 groups (bits [40*lane, 40*lane+40)) via
//    4 shuffles + funnel shift; one coalesced float4 store per lane.
//
// Bit rule: +1.0f sign 0 -> bit 1 ; -1.0f sign 1 -> bit 0.

__global__ __launch_bounds__(256)
void units2indices_warp40(const unsigned* __restrict__ in,
                          float4* __restrict__ out4,
                          int n_warps)
{
    const unsigned lane = threadIdx.x & 31u;
    const unsigned gwarp = (blockIdx.x * blockDim.x + threadIdx.x) >> 5;
    if ((int)gwarp >= n_warps) return;

    const unsigned* p = in + (size_t)gwarp * 1280 + lane;

    // Front-batched coalesced loads (each warp LDG = one 128B line).
    unsigned w[40];
    #pragma unroll
    for (int it = 0; it < 40; it++)
        w[it] = __ldcs(p + it * 32);

    // Ballot sign-transpose; lane l keeps masks l (saved0) and 32+l (saved1).
    unsigned saved0 = 0, saved1 = 0;
    #pragma unroll
    for (int it = 0; it < 40; it++) {
        unsigned mask = __ballot_sync(0xFFFFFFFFu, !(w[it] >> 31));
        if (it < 32) {
            if (lane == (unsigned)it) saved0 = mask;
        } else {
            if (lane == (unsigned)(it - 32)) saved1 = mask;
        }
    }

    // Phase 2: lane emits groups 4*lane .. 4*lane+3
    // = bits [40*lane, 40*lane+40) of the warp's 1280-bit sequence.
    const unsigned b   = 40u * lane;
    const unsigned k0  = b >> 5;          // 0..38
    const unsigned off = b & 31u;         // 0, 8, 16, 24

    // Fetch mask words k0 and k0+1 (shfl index is mod-32; select bank by k).
    unsigned a0 = __shfl_sync(0xFFFFFFFFu, saved0, (int)k0);
    unsigned b0 = __shfl_sync(0xFFFFFFFFu, saved1, (int)k0);
    unsigned a1 = __shfl_sync(0xFFFFFFFFu, saved0, (int)(k0 + 1));
    unsigned b1 = __shfl_sync(0xFFFFFFFFu, saved1, (int)(k0 + 1));
    unsigned w0 = (k0 < 32u) ? a0 : b0;
    unsigned w1 = ((k0 + 1u) < 32u) ? a1 : b1;

    // 40-bit window: off+40 <= 64 always (off <= 24).
    unsigned lo = __funnelshift_r(w0, w1, off);     // bits off..off+31
    unsigned hi = (off ? (w1 >> off) : 0u) & 0xFFu; // bits off+32..off+39
    if (off == 0) hi = w1 & 0xFFu;

    // Groups, MSB-first -> bit-reverse each 10-bit field.
    unsigned g0 = __brev(lo & 0x3FFu) >> 22;
    unsigned g1 = __brev((lo >> 10) & 0x3FFu) >> 22;
    unsigned g2 = __brev((lo >> 20) & 0x3FFu) >> 22;
    unsigned f3 = (lo >> 30) | (hi << 2);           // bits 30..39
    unsigned g3 = __brev(f3 & 0x3FFu) >> 22;

    __stcs(out4 + (size_t)gwarp * 32 + lane,
           make_float4((float)g0, (float)g1, (float)g2, (float)g3));
}

// Generic fallback (num_bits != 10, odd shapes, tails).
__global__ __launch_bounds__(256)
void units2indices_generic_f32(const unsigned* __restrict__ in,
                               float* __restrict__ out,
                               int n_groups, int num_bits, int g_start)
{
    int g = g_start + blockIdx.x * blockDim.x + threadIdx.x;
    if (g >= n_groups) return;

    const unsigned* p = in + (size_t)g * num_bits;
    int idx = 0;
    for (int i = 0; i < num_bits; i++)
        idx = (idx << 1) | (int)(1u - (p[i] >> 31));
    out[g] = (float)idx;
}

extern "C" void kernel_launch(void* const* d_in, const int* in_sizes, int n_in,
                              void* d_out, int out_size)
{
    // Input tensor = largest buffer (robust to ordering / scalar inputs).
    int imax = 0;
    for (int i = 1; i < n_in; i++)
        if (in_sizes[i] > in_sizes[imax]) imax = i;

    const unsigned* in = (const unsigned*)d_in[imax];
    float* out = (float*)d_out;

    long long n_total = (long long)in_sizes[imax];
    int num_bits = (out_size > 0) ? (int)(n_total / (long long)out_size) : 10;
    if (num_bits <= 0) num_bits = 10;

    if (num_bits == 10) {
        int n_warps = out_size / 128;   // 128 groups per warp
        if (n_warps > 0) {
            int blocks = (n_warps + 7) / 8;   // 8 warps per 256-thread block
            units2indices_warp40<<<blocks, 256>>>(in, (float4*)out, n_warps);
        }
        int done = n_warps * 128;
        int rem = out_size - done;
        if (rem > 0) {
            int blocks = (rem + 255) / 256;
            units2indices_generic_f32<<<blocks, 256>>>(
                in, out, out_size, 10, done);
        }
    } else {
        int blocks = (out_size + 255) / 256;
        units2indices_generic_f32<<<blocks, 256>>>(
            in, out, out_size, num_bits, 0);
    }
}

// round 9
// speedup vs baseline: 1.0214x; 1.0214x over previous
#include <cuda_runtime.h>
#include <cuda_bf16.h>
#include <stdint.h>

// units2indices: 80M fp32 bipolar {-1,+1} -> 8M codebook index VALUES stored
// as float32 (harness __output__ dtype is float32). Groups of num_bits=10,
// first element is MSB.
//
// CONVERGED DESIGN (R4-R8): four structurally different kernels all achieve
// 6.45-6.54 TB/s -> that is the HBM wall for this 10:1 read:write stream.
// This is the best variant: warp-autonomous ballot transpose,
//  - each warp owns 640 contiguous floats = 64 groups
//  - 20 coalesced scalar loads front-batched (1 line per warp LDG, MLP=20)
//  - 20 ballots pack sign bits; lane l retains mask l
//  - phase 2: 2 shuffles + funnel shift + brev, one float2 store per lane
//  - 512-thread blocks (fewer CTAs / wave transitions), single launch.
//
// Bit rule: +1.0f sign 0 -> bit 1 ; -1.0f sign 1 -> bit 0.

__global__ __launch_bounds__(512)
void units2indices_warp(const unsigned* __restrict__ in,
                        float2* __restrict__ out2,
                        int n_warps)
{
    const unsigned lane  = threadIdx.x & 31u;
    const unsigned gwarp = (blockIdx.x * blockDim.x + threadIdx.x) >> 5;
    if ((int)gwarp >= n_warps) return;

    const unsigned* p = in + (size_t)gwarp * 640 + lane;

    // Front-batched coalesced loads (each warp LDG = one 128B line).
    unsigned w[20];
    #pragma unroll
    for (int it = 0; it < 20; it++)
        w[it] = __ldcs(p + it * 32);

    // Ballot sign-transpose; lane l keeps the mask of iteration l.
    unsigned saved = 0;
    #pragma unroll
    for (int it = 0; it < 20; it++) {
        unsigned mask = __ballot_sync(0xFFFFFFFFu, !(w[it] >> 31));
        if (lane == (unsigned)it) saved = mask;
    }

    // Phase 2: lane emits groups (2*lane, 2*lane+1) = bits [20*lane, +20).
    const unsigned b  = 20u * lane;
    const unsigned k  = b >> 5;                 // 0..19
    const unsigned k1 = (k + 1 > 19u) ? 19u : k + 1;
    const unsigned w0 = __shfl_sync(0xFFFFFFFFu, saved, (int)k);
    const unsigned w1 = __shfl_sync(0xFFFFFFFFu, saved, (int)k1);
    const unsigned bits = __funnelshift_r(w0, w1, b & 31u);

    // First element of a group is the MSB -> bit-reverse 10-bit fields.
    unsigned g0 = __brev(bits & 0x3FFu) >> 22;
    unsigned g1 = __brev((bits >> 10) & 0x3FFu) >> 22;

    __stcs(out2 + (size_t)gwarp * 32 + lane,
           make_float2((float)g0, (float)g1));
}

// Generic fallback (num_bits != 10, odd shapes, tails).
__global__ __launch_bounds__(256)
void units2indices_generic_f32(const unsigned* __restrict__ in,
                               float* __restrict__ out,
                               int n_groups, int num_bits, int g_start)
{
    int g = g_start + blockIdx.x * blockDim.x + threadIdx.x;
    if (g >= n_groups) return;

    const unsigned* p = in + (size_t)g * num_bits;
    int idx = 0;
    for (int i = 0; i < num_bits; i++)
        idx = (idx << 1) | (int)(1u - (p[i] >> 31));
    out[g] = (float)idx;
}

extern "C" void kernel_launch(void* const* d_in, const int* in_sizes, int n_in,
                              void* d_out, int out_size)
{
    // Input tensor = largest buffer (robust to ordering / scalar inputs).
    int imax = 0;
    for (int i = 1; i < n_in; i++)
        if (in_sizes[i] > in_sizes[imax]) imax = i;

    const unsigned* in = (const unsigned*)d_in[imax];
    float* out = (float*)d_out;

    long long n_total = (long long)in_sizes[imax];
    int num_bits = (out_size > 0) ? (int)(n_total / (long long)out_size) : 10;
    if (num_bits <= 0) num_bits = 10;

    if (num_bits == 10) {
        int n_warps = out_size / 64;              // 64 groups per warp
        if (n_warps > 0) {
            int blocks = (n_warps + 15) / 16;     // 16 warps per 512-thr block
            units2indices_warp<<<blocks, 512>>>(in, (float2*)out, n_warps);
        }
        int done = n_warps * 64;
        int rem = out_size - done;
        if (rem > 0) {
            int blocks = (rem + 255) / 256;
            units2indices_generic_f32<<<blocks, 256>>>(
                in, out, out_size, 10, done);
        }
    } else {
        int blocks = (out_size + 255) / 256;
        units2indices_generic_f32<<<blocks, 256>>>(
            in, out, out_size, num_bits, 0);
    }
}